// round 1
// baseline (speedup 1.0000x reference)
#include <cuda_runtime.h>
#include <math.h>

#define NN 100000
#define DD 128
#define HH 64
#define CC 40

// Scratch (static __device__ allocation per harness rules)
__device__ float g_sum1[(size_t)NN * DD];   // 51.2 MB
__device__ float g_deg[NN];                 // 0.4 MB
__device__ float g_h[(size_t)NN * HH];      // 25.6 MB
__device__ float g_sum2[(size_t)NN * HH];   // 25.6 MB
__device__ int   g_is64;

// ---------------------------------------------------------------------------
// Detect whether edge_index is int64 or int32. If the data is int32, reading
// pairs as int64 yields values >= 2^32 with overwhelming probability
// (values are uniform in [0, 1e5)).
// ---------------------------------------------------------------------------
__global__ void k_detect(const void* __restrict__ ei) {
    const long long* p = (const long long*)ei;
    int ok = 1;
    for (int i = 0; i < 128; ++i) {
        long long v = p[i];
        if (v < 0 || v >= NN) { ok = 0; break; }
    }
    g_is64 = ok;
}

// ---------------------------------------------------------------------------
// Zero the accumulation buffers.
// ---------------------------------------------------------------------------
__global__ void k_zero() {
    int i = blockIdx.x * blockDim.x + threadIdx.x;
    float4 z = make_float4(0.f, 0.f, 0.f, 0.f);
    if (i < NN * DD / 4) ((float4*)g_sum1)[i] = z;
    if (i < NN * HH / 4) ((float4*)g_sum2)[i] = z;
    if (i < NN / 4)      ((float4*)g_deg)[i]  = z;
}

// ---------------------------------------------------------------------------
// Layer-1 edge scatter: one warp per edge. 32 lanes x float4 = 128 floats.
// red.global.add.v4.f32 = no-return vector reduction (sm_90+).
// ---------------------------------------------------------------------------
__global__ void k_scatter1(const float* __restrict__ x,
                           const void* __restrict__ ei, int nE) {
    int w = (blockIdx.x * blockDim.x + threadIdx.x) >> 5;
    int lane = threadIdx.x & 31;
    if (w >= nE) return;
    long long s, d;
    if (g_is64) {
        const long long* p = (const long long*)ei;
        s = p[w]; d = p[nE + w];
    } else {
        const int* p = (const int*)ei;
        s = p[w]; d = p[nE + w];
    }
    float4 v = __ldg((const float4*)(x + (size_t)s * DD) + lane);
    float* o = g_sum1 + (size_t)d * DD + lane * 4;
    asm volatile("red.global.add.v4.f32 [%0], {%1,%2,%3,%4};"
                 :: "l"(o), "f"(v.x), "f"(v.y), "f"(v.z), "f"(v.w) : "memory");
    if (lane == 0) atomicAdd(g_deg + d, 1.0f);
}

// ---------------------------------------------------------------------------
// Layer-1 GEMM: h = relu( (sum1/deg) @ W1l + x @ W1r + b1 )  -> g_h [N,64]
// Viewed as [agg ; x] (K=256) @ [W1l ; W1r] (256x64).
// Block tile: 64 nodes x 64 cols, 256 threads, 4x4 microtile per thread.
// ---------------------------------------------------------------------------
__global__ void k_gemm1(const float* __restrict__ x,
                        const float* __restrict__ Wl,
                        const float* __restrict__ Wr,
                        const float* __restrict__ b) {
    __shared__ float As[64][33];   // padded to dodge bank conflicts
    __shared__ float Bs[32][64];
    __shared__ float scl[64];

    int tid = threadIdx.x;
    int tx = tid & 15, ty = tid >> 4;
    int m0 = blockIdx.x * 64;

    if (tid < 64) {
        int mg = min(m0 + tid, NN - 1);
        scl[tid] = 1.0f / fmaxf(g_deg[mg], 1.0f);
    }

    float acc[4][4] = {};

    for (int c = 0; c < 8; ++c) {
        int kb = c * 32;
        __syncthreads();   // also publishes scl on first iteration
        // Load A chunk: 64 rows x 32 k. Each thread: 2 float4.
        {
            int m  = tid >> 3;
            int kk = (tid & 7) * 4;
            #pragma unroll
            for (int r = 0; r < 2; ++r, m += 32) {
                int mg = min(m0 + m, NN - 1);
                float4 v;
                if (kb < 128) {
                    v = *(const float4*)(g_sum1 + (size_t)mg * DD + kb + kk);
                    float sc = scl[m];
                    v.x *= sc; v.y *= sc; v.z *= sc; v.w *= sc;
                } else {
                    v = __ldg((const float4*)(x + (size_t)mg * DD + (kb - 128) + kk));
                }
                As[m][kk] = v.x; As[m][kk + 1] = v.y;
                As[m][kk + 2] = v.z; As[m][kk + 3] = v.w;
            }
        }
        // Load B chunk: 32 k-rows x 64 cols. Each thread: 8 floats.
        {
            int k = tid >> 3;
            int n = (tid & 7) * 8;
            const float* W = (kb < 128) ? (Wl + (size_t)kb * 64)
                                        : (Wr + (size_t)(kb - 128) * 64);
            float4 v0 = __ldg((const float4*)(W + k * 64 + n));
            float4 v1 = __ldg((const float4*)(W + k * 64 + n + 4));
            *(float4*)&Bs[k][n]     = v0;
            *(float4*)&Bs[k][n + 4] = v1;
        }
        __syncthreads();
        #pragma unroll
        for (int kk = 0; kk < 32; ++kk) {
            float a0 = As[ty * 4 + 0][kk];
            float a1 = As[ty * 4 + 1][kk];
            float a2 = As[ty * 4 + 2][kk];
            float a3 = As[ty * 4 + 3][kk];
            float4 bv = *(float4*)&Bs[kk][tx * 4];
            acc[0][0] += a0 * bv.x; acc[0][1] += a0 * bv.y; acc[0][2] += a0 * bv.z; acc[0][3] += a0 * bv.w;
            acc[1][0] += a1 * bv.x; acc[1][1] += a1 * bv.y; acc[1][2] += a1 * bv.z; acc[1][3] += a1 * bv.w;
            acc[2][0] += a2 * bv.x; acc[2][1] += a2 * bv.y; acc[2][2] += a2 * bv.z; acc[2][3] += a2 * bv.w;
            acc[3][0] += a3 * bv.x; acc[3][1] += a3 * bv.y; acc[3][2] += a3 * bv.z; acc[3][3] += a3 * bv.w;
        }
    }

    float4 bb = *(const float4*)(b + tx * 4);
    #pragma unroll
    for (int i = 0; i < 4; ++i) {
        int mg = m0 + ty * 4 + i;
        if (mg < NN) {
            float4 o;
            o.x = fmaxf(acc[i][0] + bb.x, 0.f);
            o.y = fmaxf(acc[i][1] + bb.y, 0.f);
            o.z = fmaxf(acc[i][2] + bb.z, 0.f);
            o.w = fmaxf(acc[i][3] + bb.w, 0.f);
            *(float4*)(g_h + (size_t)mg * HH + tx * 4) = o;
        }
    }
}

// ---------------------------------------------------------------------------
// Layer-2 edge scatter: one warp per edge, 32 lanes x float2 = 64 floats.
// ---------------------------------------------------------------------------
__global__ void k_scatter2(const void* __restrict__ ei, int nE) {
    int w = (blockIdx.x * blockDim.x + threadIdx.x) >> 5;
    int lane = threadIdx.x & 31;
    if (w >= nE) return;
    long long s, d;
    if (g_is64) {
        const long long* p = (const long long*)ei;
        s = p[w]; d = p[nE + w];
    } else {
        const int* p = (const int*)ei;
        s = p[w]; d = p[nE + w];
    }
    float2 v = *((const float2*)(g_h + (size_t)s * HH) + lane);
    float* o = g_sum2 + (size_t)d * HH + lane * 2;
    asm volatile("red.global.add.v2.f32 [%0], {%1,%2};"
                 :: "l"(o), "f"(v.x), "f"(v.y) : "memory");
}

// ---------------------------------------------------------------------------
// Layer-2 GEMM + fused log_softmax. Warp per node, K=64+64, 40 output cols:
// lane -> col lane, lanes 0..7 also col 32+lane.
// ---------------------------------------------------------------------------
__global__ void k_gemm2(const float* __restrict__ Wl,
                        const float* __restrict__ Wr,
                        const float* __restrict__ b,
                        float* __restrict__ out) {
    __shared__ float sWl[64 * 40];
    __shared__ float sWr[64 * 40];
    __shared__ float sb[40];
    int tid = threadIdx.x;
    for (int i = tid; i < 64 * 40; i += blockDim.x) { sWl[i] = Wl[i]; sWr[i] = Wr[i]; }
    if (tid < 40) sb[tid] = b[tid];
    __syncthreads();

    int w = (blockIdx.x * blockDim.x + tid) >> 5;
    int lane = tid & 31;
    if (w >= NN) return;

    const float* ag = g_sum2 + (size_t)w * HH;
    const float* hr = g_h    + (size_t)w * HH;
    float sc = 1.0f / fmaxf(g_deg[w], 1.0f);
    float a0 = ag[lane] * sc, a1 = ag[lane + 32] * sc;
    float h0 = hr[lane],       h1 = hr[lane + 32];

    float z0 = 0.f, z1 = 0.f;
    #pragma unroll
    for (int k = 0; k < 32; ++k) {
        float av = __shfl_sync(0xffffffffu, a0, k);
        float hv = __shfl_sync(0xffffffffu, h0, k);
        z0 += av * sWl[k * 40 + lane] + hv * sWr[k * 40 + lane];
        if (lane < 8)
            z1 += av * sWl[k * 40 + 32 + lane] + hv * sWr[k * 40 + 32 + lane];
    }
    #pragma unroll
    for (int k = 0; k < 32; ++k) {
        float av = __shfl_sync(0xffffffffu, a1, k);
        float hv = __shfl_sync(0xffffffffu, h1, k);
        int kr = k + 32;
        z0 += av * sWl[kr * 40 + lane] + hv * sWr[kr * 40 + lane];
        if (lane < 8)
            z1 += av * sWl[kr * 40 + 32 + lane] + hv * sWr[kr * 40 + 32 + lane];
    }

    z0 += sb[lane];
    if (lane < 8) z1 += sb[32 + lane]; else z1 = -INFINITY;

    float m = fmaxf(z0, z1);
    #pragma unroll
    for (int o = 16; o; o >>= 1) m = fmaxf(m, __shfl_xor_sync(0xffffffffu, m, o));
    float e = expf(z0 - m) + (lane < 8 ? expf(z1 - m) : 0.f);
    #pragma unroll
    for (int o = 16; o; o >>= 1) e += __shfl_xor_sync(0xffffffffu, e, o);
    float lse = logf(e) + m;

    out[(size_t)w * CC + lane] = z0 - lse;
    if (lane < 8) out[(size_t)w * CC + 32 + lane] = z1 - lse;
}

// ---------------------------------------------------------------------------
extern "C" void kernel_launch(void* const* d_in, const int* in_sizes, int n_in,
                              void* d_out, int out_size) {
    const float* x   = (const float*)d_in[0];
    const void*  ei  = d_in[1];
    const float* W1l = (const float*)d_in[2];
    const float* W1r = (const float*)d_in[3];
    const float* b1  = (const float*)d_in[4];
    const float* W2l = (const float*)d_in[5];
    const float* W2r = (const float*)d_in[6];
    const float* b2  = (const float*)d_in[7];
    float* out = (float*)d_out;

    int nE = in_sizes[1] / 2;

    k_detect<<<1, 1>>>(ei);
    k_zero<<<(NN * DD / 4 + 255) / 256, 256>>>();
    {
        long long thr = (long long)nE * 32;
        int blocks = (int)((thr + 255) / 256);
        k_scatter1<<<blocks, 256>>>(x, ei, nE);
        k_gemm1<<<(NN + 63) / 64, 256>>>(x, W1l, W1r, b1);
        k_scatter2<<<blocks, 256>>>(ei, nE);
        k_gemm2<<<(NN + 7) / 8, 256>>>(W2l, W2r, b2, out);
    }
}

// round 2
// speedup vs baseline: 1.5965x; 1.5965x over previous
#include <cuda_runtime.h>
#include <math.h>

#define NN 100000
#define DD 128
#define HH 64
#define CC 40
#define NB 391          // ceil(NN/256) scan blocks

// ---- scratch (__device__ globals per harness rules) ----
__device__ float g_agg1[(size_t)NN * DD];   // 51.2 MB (pre-scaled mean agg, layer1)
__device__ float g_h[(size_t)NN * HH];      // 25.6 MB
__device__ float g_agg2[(size_t)NN * HH];   // 25.6 MB
__device__ int   g_cnt[NN];                 // degree (int)
__device__ int   g_rowptr[NN];              // CSR row starts
__device__ int   g_cur[NN];                 // fill cursors
__device__ float g_invdeg[NN];
__device__ int   g_srcs[2000000];           // CSR source lists (E <= 2M)
__device__ int   g_exc[NB * 256];
__device__ int   g_bsum[512];
__device__ int   g_boff[512];
__device__ int   g_is64;

// ---------------------------------------------------------------------------
// Detect int64 vs int32 edge_index (int32 pairs read as int64 are >= 2^32
// with overwhelming probability for uniform values in [0, 1e5)).
// ---------------------------------------------------------------------------
__global__ void k_detect(const void* __restrict__ ei) {
    const long long* p = (const long long*)ei;
    int ok = 1;
    for (int i = 0; i < 128; ++i) {
        long long v = p[i];
        if (v < 0 || v >= NN) { ok = 0; break; }
    }
    g_is64 = ok;
}

__global__ void k_zero_cnt() {
    int i = blockIdx.x * blockDim.x + threadIdx.x;
    if (i < NN) g_cnt[i] = 0;
}

// ---------------------------------------------------------------------------
// CSR build: histogram -> 2-level exclusive scan -> atomic fill
// ---------------------------------------------------------------------------
__global__ void k_hist(const void* __restrict__ ei, int nE) {
    int e = blockIdx.x * blockDim.x + threadIdx.x;
    if (e >= nE) return;
    int d = g_is64 ? (int)((const long long*)ei)[nE + e]
                   : ((const int*)ei)[nE + e];
    atomicAdd(&g_cnt[d], 1);
}

__global__ void k_scan1() {   // 391 blocks x 256
    __shared__ int sh[256];
    int t = threadIdx.x, b = blockIdx.x;
    int i = b * 256 + t;
    int v = (i < NN) ? g_cnt[i] : 0;
    sh[t] = v;
    __syncthreads();
    #pragma unroll
    for (int off = 1; off < 256; off <<= 1) {
        int u = (t >= off) ? sh[t - off] : 0;
        __syncthreads();
        sh[t] += u;
        __syncthreads();
    }
    if (i < NN) g_exc[i] = sh[t] - v;
    if (t == 255) g_bsum[b] = sh[t];
}

__global__ void k_scan2() {   // 1 block x 512
    __shared__ int sh[512];
    int t = threadIdx.x;
    int v = (t < NB) ? g_bsum[t] : 0;
    sh[t] = v;
    __syncthreads();
    #pragma unroll
    for (int off = 1; off < 512; off <<= 1) {
        int u = (t >= off) ? sh[t - off] : 0;
        __syncthreads();
        sh[t] += u;
        __syncthreads();
    }
    g_boff[t] = sh[t] - v;
}

__global__ void k_scan3() {
    int i = blockIdx.x * blockDim.x + threadIdx.x;
    if (i >= NN) return;
    int row = g_exc[i] + g_boff[i >> 8];
    g_rowptr[i] = row;
    g_cur[i] = row;
    g_invdeg[i] = 1.0f / fmaxf((float)g_cnt[i], 1.0f);
}

__global__ void k_fill(const void* __restrict__ ei, int nE) {
    int e = blockIdx.x * blockDim.x + threadIdx.x;
    if (e >= nE) return;
    int s, d;
    if (g_is64) {
        const long long* p = (const long long*)ei;
        s = (int)p[e]; d = (int)p[nE + e];
    } else {
        const int* p = (const int*)ei;
        s = p[e]; d = p[nE + e];
    }
    int pos = atomicAdd(&g_cur[d], 1);
    g_srcs[pos] = s;
}

// ---------------------------------------------------------------------------
// Layer-1 aggregation: warp per node, lane covers 4 features (float4).
// agg1[n] = (1/deg) * sum_{s in nbrs(n)} x[s]
// ---------------------------------------------------------------------------
__global__ void k_agg1(const float* __restrict__ x) {
    int w = (blockIdx.x * blockDim.x + threadIdx.x) >> 5;
    int lane = threadIdx.x & 31;
    if (w >= NN) return;
    int beg = g_rowptr[w], n = g_cnt[w];
    const float4* xb = (const float4*)x;
    float4 a0 = make_float4(0.f, 0.f, 0.f, 0.f);
    float4 a1 = make_float4(0.f, 0.f, 0.f, 0.f);
    int e = 0;
    for (; e + 1 < n; e += 2) {
        int s0 = g_srcs[beg + e];
        int s1 = g_srcs[beg + e + 1];
        float4 v0 = __ldg(xb + (size_t)s0 * 32 + lane);
        float4 v1 = __ldg(xb + (size_t)s1 * 32 + lane);
        a0.x += v0.x; a0.y += v0.y; a0.z += v0.z; a0.w += v0.w;
        a1.x += v1.x; a1.y += v1.y; a1.z += v1.z; a1.w += v1.w;
    }
    if (e < n) {
        int s0 = g_srcs[beg + e];
        float4 v0 = __ldg(xb + (size_t)s0 * 32 + lane);
        a0.x += v0.x; a0.y += v0.y; a0.z += v0.z; a0.w += v0.w;
    }
    float sc = g_invdeg[w];
    float4 o;
    o.x = (a0.x + a1.x) * sc; o.y = (a0.y + a1.y) * sc;
    o.z = (a0.z + a1.z) * sc; o.w = (a0.w + a1.w) * sc;
    ((float4*)g_agg1)[(size_t)w * 32 + lane] = o;
}

// ---------------------------------------------------------------------------
// Layer-2 aggregation: warp per node, lane covers 2 features (float2).
// ---------------------------------------------------------------------------
__global__ void k_agg2() {
    int w = (blockIdx.x * blockDim.x + threadIdx.x) >> 5;
    int lane = threadIdx.x & 31;
    if (w >= NN) return;
    int beg = g_rowptr[w], n = g_cnt[w];
    const float2* hb = (const float2*)g_h;
    float2 a0 = make_float2(0.f, 0.f);
    float2 a1 = make_float2(0.f, 0.f);
    int e = 0;
    for (; e + 1 < n; e += 2) {
        int s0 = g_srcs[beg + e];
        int s1 = g_srcs[beg + e + 1];
        float2 v0 = __ldg(hb + (size_t)s0 * 32 + lane);
        float2 v1 = __ldg(hb + (size_t)s1 * 32 + lane);
        a0.x += v0.x; a0.y += v0.y;
        a1.x += v1.x; a1.y += v1.y;
    }
    if (e < n) {
        int s0 = g_srcs[beg + e];
        float2 v0 = __ldg(hb + (size_t)s0 * 32 + lane);
        a0.x += v0.x; a0.y += v0.y;
    }
    float sc = g_invdeg[w];
    float2 o;
    o.x = (a0.x + a1.x) * sc;
    o.y = (a0.y + a1.y) * sc;
    ((float2*)g_agg2)[(size_t)w * 32 + lane] = o;
}

// ---------------------------------------------------------------------------
// Layer-1 GEMM: h = relu( [agg1 ; x] @ [W1l ; W1r] + b1 )  -> g_h [N,64]
// Block tile 64x64, 256 threads, 4x4 microtile.
// ---------------------------------------------------------------------------
__global__ void k_gemm1(const float* __restrict__ x,
                        const float* __restrict__ Wl,
                        const float* __restrict__ Wr,
                        const float* __restrict__ b) {
    __shared__ float As[64][33];
    __shared__ float Bs[32][64];

    int tid = threadIdx.x;
    int tx = tid & 15, ty = tid >> 4;
    int m0 = blockIdx.x * 64;

    float acc[4][4] = {};

    for (int c = 0; c < 8; ++c) {
        int kb = c * 32;
        __syncthreads();
        {
            int m  = tid >> 3;
            int kk = (tid & 7) * 4;
            #pragma unroll
            for (int r = 0; r < 2; ++r, m += 32) {
                int mg = min(m0 + m, NN - 1);
                float4 v;
                if (kb < 128) {
                    v = *(const float4*)(g_agg1 + (size_t)mg * DD + kb + kk);
                } else {
                    v = __ldg((const float4*)(x + (size_t)mg * DD + (kb - 128) + kk));
                }
                As[m][kk] = v.x; As[m][kk + 1] = v.y;
                As[m][kk + 2] = v.z; As[m][kk + 3] = v.w;
            }
        }
        {
            int k = tid >> 3;
            int n = (tid & 7) * 8;
            const float* W = (kb < 128) ? (Wl + (size_t)kb * 64)
                                        : (Wr + (size_t)(kb - 128) * 64);
            float4 v0 = __ldg((const float4*)(W + k * 64 + n));
            float4 v1 = __ldg((const float4*)(W + k * 64 + n + 4));
            *(float4*)&Bs[k][n]     = v0;
            *(float4*)&Bs[k][n + 4] = v1;
        }
        __syncthreads();
        #pragma unroll
        for (int kk = 0; kk < 32; ++kk) {
            float a0 = As[ty * 4 + 0][kk];
            float a1 = As[ty * 4 + 1][kk];
            float a2 = As[ty * 4 + 2][kk];
            float a3 = As[ty * 4 + 3][kk];
            float4 bv = *(float4*)&Bs[kk][tx * 4];
            acc[0][0] += a0 * bv.x; acc[0][1] += a0 * bv.y; acc[0][2] += a0 * bv.z; acc[0][3] += a0 * bv.w;
            acc[1][0] += a1 * bv.x; acc[1][1] += a1 * bv.y; acc[1][2] += a1 * bv.z; acc[1][3] += a1 * bv.w;
            acc[2][0] += a2 * bv.x; acc[2][1] += a2 * bv.y; acc[2][2] += a2 * bv.z; acc[2][3] += a2 * bv.w;
            acc[3][0] += a3 * bv.x; acc[3][1] += a3 * bv.y; acc[3][2] += a3 * bv.z; acc[3][3] += a3 * bv.w;
        }
    }

    float4 bb = *(const float4*)(b + tx * 4);
    #pragma unroll
    for (int i = 0; i < 4; ++i) {
        int mg = m0 + ty * 4 + i;
        if (mg < NN) {
            float4 o;
            o.x = fmaxf(acc[i][0] + bb.x, 0.f);
            o.y = fmaxf(acc[i][1] + bb.y, 0.f);
            o.z = fmaxf(acc[i][2] + bb.z, 0.f);
            o.w = fmaxf(acc[i][3] + bb.w, 0.f);
            *(float4*)(g_h + (size_t)mg * HH + tx * 4) = o;
        }
    }
}

// ---------------------------------------------------------------------------
// Layer-2 GEMM + fused log_softmax. Warp per node.
// ---------------------------------------------------------------------------
__global__ void k_gemm2(const float* __restrict__ Wl,
                        const float* __restrict__ Wr,
                        const float* __restrict__ b,
                        float* __restrict__ out) {
    __shared__ float sWl[64 * 40];
    __shared__ float sWr[64 * 40];
    __shared__ float sb[40];
    int tid = threadIdx.x;
    for (int i = tid; i < 64 * 40; i += blockDim.x) { sWl[i] = Wl[i]; sWr[i] = Wr[i]; }
    if (tid < 40) sb[tid] = b[tid];
    __syncthreads();

    int w = (blockIdx.x * blockDim.x + tid) >> 5;
    int lane = tid & 31;
    if (w >= NN) return;

    const float* ag = g_agg2 + (size_t)w * HH;
    const float* hr = g_h    + (size_t)w * HH;
    float a0 = ag[lane], a1 = ag[lane + 32];
    float h0 = hr[lane], h1 = hr[lane + 32];

    float z0 = 0.f, z1 = 0.f;
    #pragma unroll
    for (int k = 0; k < 32; ++k) {
        float av = __shfl_sync(0xffffffffu, a0, k);
        float hv = __shfl_sync(0xffffffffu, h0, k);
        z0 += av * sWl[k * 40 + lane] + hv * sWr[k * 40 + lane];
        if (lane < 8)
            z1 += av * sWl[k * 40 + 32 + lane] + hv * sWr[k * 40 + 32 + lane];
    }
    #pragma unroll
    for (int k = 0; k < 32; ++k) {
        float av = __shfl_sync(0xffffffffu, a1, k);
        float hv = __shfl_sync(0xffffffffu, h1, k);
        int kr = k + 32;
        z0 += av * sWl[kr * 40 + lane] + hv * sWr[kr * 40 + lane];
        if (lane < 8)
            z1 += av * sWl[kr * 40 + 32 + lane] + hv * sWr[kr * 40 + 32 + lane];
    }

    z0 += sb[lane];
    if (lane < 8) z1 += sb[32 + lane]; else z1 = -INFINITY;

    float m = fmaxf(z0, z1);
    #pragma unroll
    for (int o = 16; o; o >>= 1) m = fmaxf(m, __shfl_xor_sync(0xffffffffu, m, o));
    float e = expf(z0 - m) + (lane < 8 ? expf(z1 - m) : 0.f);
    #pragma unroll
    for (int o = 16; o; o >>= 1) e += __shfl_xor_sync(0xffffffffu, e, o);
    float lse = logf(e) + m;

    out[(size_t)w * CC + lane] = z0 - lse;
    if (lane < 8) out[(size_t)w * CC + 32 + lane] = z1 - lse;
}

// ---------------------------------------------------------------------------
extern "C" void kernel_launch(void* const* d_in, const int* in_sizes, int n_in,
                              void* d_out, int out_size) {
    const float* x   = (const float*)d_in[0];
    const void*  ei  = d_in[1];
    const float* W1l = (const float*)d_in[2];
    const float* W1r = (const float*)d_in[3];
    const float* b1  = (const float*)d_in[4];
    const float* W2l = (const float*)d_in[5];
    const float* W2r = (const float*)d_in[6];
    const float* b2  = (const float*)d_in[7];
    float* out = (float*)d_out;

    int nE = in_sizes[1] / 2;
    int eBlocks = (nE + 255) / 256;
    int nWarpBlocks = (NN * 32 + 255) / 256;

    k_detect<<<1, 1>>>(ei);
    k_zero_cnt<<<(NN + 255) / 256, 256>>>();
    k_hist<<<eBlocks, 256>>>(ei, nE);
    k_scan1<<<NB, 256>>>();
    k_scan2<<<1, 512>>>();
    k_scan3<<<(NN + 255) / 256, 256>>>();
    k_fill<<<eBlocks, 256>>>(ei, nE);

    k_agg1<<<nWarpBlocks, 256>>>(x);
    k_gemm1<<<(NN + 63) / 64, 256>>>(x, W1l, W1r, b1);
    k_agg2<<<nWarpBlocks, 256>>>();
    k_gemm2<<<(NN + 7) / 8, 256>>>(W2l, W2r, b2, out);
}